// round 6
// baseline (speedup 1.0000x reference)
#include <cuda_runtime.h>

// PatchChamferDistance: B=32, G=64, P=256, D=3 (fp32)
// d2[i][j] = max(|p_i|^2 + |q_j|^2 - 2 p_i.q_j, 0)
// out = mean_patch( mean_i min_j d2 + mean_j min_i d2 )
//
// R6: direction-split warps. 1 patch / 128-thr CTA.
//   threads 0-63: forward  (each owns 4 pred rows, scans targets)
//   threads 64-127: backward (each owns 4 tgt rows, scans preds)
// Pair-packed prescaled smem (16B/point):
//   A[jj] = {-2x_j0,-2x_j1, -2y_j0,-2y_j1},  B[jj] = {-2z_j0,-2z_j1, w_j0, w_j1}
// fma2 chain per owned row vs 2 scan points:
//   acc = fma2(z2, B.x, fma2(y2, A.y, fma2(x2, A.x, B.y)))  -> {w-2dot}x2
// Own norm added after the loop (constant over scan).

#define BGQ   2048
#define NP    256
#define NPAIR 128
#define T     128
#define INF   3.402823e38f

typedef unsigned long long u64;

__device__ __forceinline__ u64 pk2(float a, float b) {
    u64 r;
    asm("mov.b64 %0, {%1, %2};" : "=l"(r) : "f"(a), "f"(b));
    return r;
}
__device__ __forceinline__ u64 fma2(u64 a, u64 b, u64 c) {
    u64 d;
    asm("fma.rn.f32x2 %0, %1, %2, %3;" : "=l"(d) : "l"(a), "l"(b), "l"(c));
    return d;
}
__device__ __forceinline__ void upk2(u64 v, float& lo, float& hi) {
    asm("mov.b64 {%0, %1}, %2;" : "=f"(lo), "=f"(hi) : "l"(v));
}

__global__ void pcd_zero_kernel(float* out) { out[0] = 0.0f; }

__global__ __launch_bounds__(T)
void pcd_chamfer_kernel(const float* __restrict__ pred,
                        const float* __restrict__ tgt,
                        float* __restrict__ out)
{
    __shared__ ulonglong2 spA[NPAIR], spB[NPAIR];   // preds  (pair-packed)
    __shared__ ulonglong2 sqA[NPAIR], sqB[NPAIR];   // targets
    __shared__ float wsum[T / 32];

    const int t     = threadIdx.x;
    const int patch = blockIdx.x;

    const float* pb = pred + (size_t)patch * NP * 3;
    const float* qb = tgt  + (size_t)patch * NP * 3;

    // phase 1: thread t loads point pair (2t, 2t+1) of both clouds
    {
        int j0 = 2 * t;
        float x0 = pb[j0 * 3 + 0], y0 = pb[j0 * 3 + 1], z0 = pb[j0 * 3 + 2];
        float x1 = pb[j0 * 3 + 3], y1 = pb[j0 * 3 + 4], z1 = pb[j0 * 3 + 5];
        float w0 = x0 * x0 + y0 * y0 + z0 * z0;
        float w1 = x1 * x1 + y1 * y1 + z1 * z1;
        spA[t] = make_ulonglong2(pk2(-2.f * x0, -2.f * x1), pk2(-2.f * y0, -2.f * y1));
        spB[t] = make_ulonglong2(pk2(-2.f * z0, -2.f * z1), pk2(w0, w1));

        x0 = qb[j0 * 3 + 0]; y0 = qb[j0 * 3 + 1]; z0 = qb[j0 * 3 + 2];
        x1 = qb[j0 * 3 + 3]; y1 = qb[j0 * 3 + 4]; z1 = qb[j0 * 3 + 5];
        w0 = x0 * x0 + y0 * y0 + z0 * z0;
        w1 = x1 * x1 + y1 * y1 + z1 * z1;
        sqA[t] = make_ulonglong2(pk2(-2.f * x0, -2.f * x1), pk2(-2.f * y0, -2.f * y1));
        sqB[t] = make_ulonglong2(pk2(-2.f * z0, -2.f * z1), pk2(w0, w1));
    }
    __syncthreads();

    const int dir = t >> 6;          // 0 = forward (own pred), 1 = backward (own tgt)
    const int t2  = t & 63;

    const ulonglong2* ownA  = dir ? sqA : spA;
    const ulonglong2* ownB  = dir ? sqB : spB;
    const ulonglong2* scanA = dir ? spA : sqA;
    const ulonglong2* scanB = dir ? spB : sqB;

    // phase 2: recover own 4 rows from smem (pairs t2 and t2+64), pack {v,v}
    u64 x2[4], y2[4], z2[4];
    float wn[4];
#pragma unroll
    for (int h = 0; h < 2; h++) {
        ulonglong2 a = ownA[t2 + 64 * h];
        ulonglong2 b = ownB[t2 + 64 * h];
        float m2x0, m2x1, m2y0, m2y1, m2z0, m2z1, w0, w1;
        upk2(a.x, m2x0, m2x1);
        upk2(a.y, m2y0, m2y1);
        upk2(b.x, m2z0, m2z1);
        upk2(b.y, w0, w1);
        float xx0 = -0.5f * m2x0, xx1 = -0.5f * m2x1;
        float yy0 = -0.5f * m2y0, yy1 = -0.5f * m2y1;
        float zz0 = -0.5f * m2z0, zz1 = -0.5f * m2z1;
        x2[2 * h]     = pk2(xx0, xx0);
        x2[2 * h + 1] = pk2(xx1, xx1);
        y2[2 * h]     = pk2(yy0, yy0);
        y2[2 * h + 1] = pk2(yy1, yy1);
        z2[2 * h]     = pk2(zz0, zz0);
        z2[2 * h + 1] = pk2(zz1, zz1);
        wn[2 * h] = w0;
        wn[2 * h + 1] = w1;
    }

    float mn[4] = {INF, INF, INF, INF};   // min over scan of (w_scan - 2 dot)

#pragma unroll 4
    for (int jj = 0; jj < NPAIR; jj++) {
        ulonglong2 a = scanA[jj];    // warp-uniform -> LDS broadcast
        ulonglong2 b = scanB[jj];
#pragma unroll
        for (int r = 0; r < 4; r++) {
            u64 acc = fma2(x2[r], a.x, b.y);
            acc = fma2(y2[r], a.y, acc);
            acc = fma2(z2[r], b.x, acc);
            float d0, d1; upk2(acc, d0, d1);
            mn[r] = fminf(mn[r], fminf(d0, d1));
        }
    }

    // add own norms, clamp (commutes with min), sum this thread's 4 rows
    float v = fmaxf(wn[0] + mn[0], 0.f) + fmaxf(wn[1] + mn[1], 0.f)
            + fmaxf(wn[2] + mn[2], 0.f) + fmaxf(wn[3] + mn[3], 0.f);

    // block reduction: 4 warps (fwd warps 0-1, bwd warps 2-3; sum is direction-agnostic)
#pragma unroll
    for (int o = 16; o > 0; o >>= 1)
        v += __shfl_down_sync(0xffffffffu, v, o);
    if ((t & 31) == 0) wsum[t >> 5] = v;
    __syncthreads();
    if (t == 0) {
        float s = wsum[0] + wsum[1] + wsum[2] + wsum[3];
        atomicAdd(out, s * (1.0f / ((float)NP * (float)BGQ)));
    }
}

extern "C" void kernel_launch(void* const* d_in, const int* in_sizes, int n_in,
                              void* d_out, int out_size)
{
    const float* pred = (const float*)d_in[0];
    const float* tgt  = (const float*)d_in[1];
    float* out = (float*)d_out;

    pcd_zero_kernel<<<1, 1>>>(out);
    pcd_chamfer_kernel<<<BGQ, T>>>(pred, tgt, out);
}